// round 10
// baseline (speedup 1.0000x reference)
#include <cuda_runtime.h>
#include <cuda_fp16.h>

// HashEmbedding: out[t, d] = sum_{h=0..3} weight_table[x[t,h] + 513*h] * emb_table[x[t,h]>>1][d]
// x is int32.
// R10: fp16 table SPLIT into 2 column chunks (64 KB each) so smem/CTA = 72.2 KB
// -> 3 CTAs x 512 threads = 48 warps/SM (vs 32 in R7-R9), combining the fp16
// traffic win with high occupancy. Sync-free warp-per-(token,chunk), depth-1
// index prefetch. Per-warp-task: 1 LDG + 4 weight LDS + 4 gather LDS.64 +
// 1 STG.128 per lane.

#define NUM_HASHES 4
#define D 256
#define CH 128                 // columns per chunk
#define W_TABLE 2052           // 512*4 + 4
#define EMB_ROWS 256
#define BLOCK_THREADS 512
#define WARPS_PER_BLOCK (BLOCK_THREADS / 32)
#define GRID_X 222             // x-blocks per chunk; 222*2 = 444 = 3 CTAs x 148 SMs

// smem byte offsets
#define OFF_W     0
#define OFF_EMB   ((W_TABLE * 4 + 15) & ~15)                 // 8208
#define SMEM_BYTES (OFF_EMB + EMB_ROWS * CH * 2)             // + 64 KB fp16 slice

__global__ __launch_bounds__(BLOCK_THREADS, 3)
void hash_embedding_kernel(const int* __restrict__ x,
                           const float* __restrict__ weight_table,
                           const float* __restrict__ emb_table,
                           float* __restrict__ out,
                           int ntok)
{
    extern __shared__ char smem[];
    float* s_w   = reinterpret_cast<float*>(smem + OFF_W);
    char*  s_emb = smem + OFF_EMB;          // [256 rows][128 halves] = 256 B/row

    const int tid   = threadIdx.x;
    const int chunk = blockIdx.y;           // 0 or 1
    const int c0    = chunk * CH;

    // ---- prologue: stage weight table (f32) ----
    for (int i = tid; i < W_TABLE; i += BLOCK_THREADS) s_w[i] = weight_table[i];

    // ---- prologue: stage this chunk's emb slice as fp16 ----
    // 256 rows x 128 cols -> 8192 float4 groups, 16 per thread.
    for (int i = tid; i < EMB_ROWS * CH / 4; i += BLOCK_THREADS) {
        const int r  = i >> 5;          // row        (CH/4 = 32 groups per row)
        const int c4 = i & 31;          // float4 group within row
        const float4 v = *reinterpret_cast<const float4*>(emb_table + r * D + c0 + c4 * 4);
        __half2 h0 = __floats2half2_rn(v.x, v.y);
        __half2 h1 = __floats2half2_rn(v.z, v.w);
        uint2 packed;
        packed.x = *reinterpret_cast<unsigned int*>(&h0);
        packed.y = *reinterpret_cast<unsigned int*>(&h1);
        *reinterpret_cast<uint2*>(s_emb + r * 256 + c4 * 8) = packed;
    }
    __syncthreads();   // the ONLY block-wide sync

    const int lane = tid & 31;
    const int gw   = blockIdx.x * WARPS_PER_BLOCK + (tid >> 5);  // warp id within chunk
    const int nw   = GRID_X * WARPS_PER_BLOCK;                   // 3552 warps per chunk

    const int off = lane * 8;           // row bytes for cols [lane*4 .. lane*4+3]

    int t = gw;
    if (t >= ntok) return;

    // depth-1 index prefetch
    int4 xi = *reinterpret_cast<const int4*>(x + (long long)t * NUM_HASHES);

    #pragma unroll 1
    for (; t < ntok; t += nw) {
        const int tn = (t + nw < ntok) ? (t + nw) : t;
        const int4 xi_next = *reinterpret_cast<const int4*>(x + (long long)tn * NUM_HASHES);

        // per-sample weights (broadcast LDS)
        const float w0 = s_w[xi.x];
        const float w1 = s_w[xi.y + 513];
        const float w2 = s_w[xi.z + 1026];
        const float w3 = s_w[xi.w + 1539];

        // fp16 row bases (idx = x >> 1; 256 B per row slice)
        const char* r0 = s_emb + ((xi.x >> 1) << 8);
        const char* r1 = s_emb + ((xi.y >> 1) << 8);
        const char* r2 = s_emb + ((xi.z >> 1) << 8);
        const char* r3 = s_emb + ((xi.w >> 1) << 8);

        // batch the 4 gather loads (LDS.64, two conflict-free phases each)
        uint2 g0 = *reinterpret_cast<const uint2*>(r0 + off);
        uint2 g1 = *reinterpret_cast<const uint2*>(r1 + off);
        uint2 g2 = *reinterpret_cast<const uint2*>(r2 + off);
        uint2 g3 = *reinterpret_cast<const uint2*>(r3 + off);

        float a0 = 0.f, a1 = 0.f, a2 = 0.f, a3 = 0.f;

        #define ACC(g, w)                                                         \
        {                                                                         \
            float2 f0 = __half22float2(*reinterpret_cast<__half2*>(&(g).x));      \
            float2 f1 = __half22float2(*reinterpret_cast<__half2*>(&(g).y));      \
            a0 += (w) * f0.x;  a1 += (w) * f0.y;                                  \
            a2 += (w) * f1.x;  a3 += (w) * f1.y;                                  \
        }
        ACC(g0, w0)
        ACC(g1, w1)
        ACC(g2, w2)
        ACC(g3, w3)
        #undef ACC

        *reinterpret_cast<float4*>(out + (long long)t * D + c0 + lane * 4) =
            make_float4(a0, a1, a2, a3);

        xi = xi_next;
    }
}

extern "C" void kernel_launch(void* const* d_in, const int* in_sizes, int n_in,
                              void* d_out, int out_size)
{
    const int*   x            = (const int*)d_in[0];
    const float* weight_table = (const float*)d_in[1];
    const float* emb_table    = (const float*)d_in[2];
    float*       out          = (float*)d_out;

    const int ntok = in_sizes[0] / NUM_HASHES;   // 65536

    cudaFuncSetAttribute(hash_embedding_kernel,
                         cudaFuncAttributeMaxDynamicSharedMemorySize, SMEM_BYTES);

    dim3 grid(GRID_X, D / CH);   // (222, 2) = 444 CTAs = 3 per SM
    hash_embedding_kernel<<<grid, BLOCK_THREADS, SMEM_BYTES>>>(
        x, weight_table, emb_table, out, ntok);
}

// round 11
// speedup vs baseline: 1.2159x; 1.2159x over previous
#include <cuda_runtime.h>
#include <cuda_fp16.h>

// HashEmbedding: out[t, d] = sum_{h=0..3} weight_table[x[t,h] + 513*h] * emb_table[x[t,h]>>1][d]
// x is int32.
// R11: R8 loop (champion: fp16 full table in smem, pair-ILP, sync-free) with the
// staging prologue rebuilt:
//   (1) helper kernel pre-converts the f32 emb table to fp16 ONCE into a
//       __device__ global (removes 148x conversion work + halves staging reads),
//   (2) main kernel stages the 128 KB fp16 table via one cp.async.bulk G2S
//       (async, zero per-thread copy instructions), weights via plain loads.

#define NUM_HASHES 4
#define D 256
#define W_TABLE 2052           // 512*4 + 4
#define EMB_ROWS 256
#define BLOCK_THREADS 1024
#define WARPS_PER_BLOCK (BLOCK_THREADS / 32)
#define GRID_X 148

#define EMB_BYTES (EMB_ROWS * D * 2)      // 131072

// smem byte offsets
#define OFF_W     0
#define OFF_MBAR  ((W_TABLE * 4 + 15) & ~15)          // 8208
#define OFF_EMB   8320                                 // 128-aligned
#define SMEM_BYTES (OFF_EMB + EMB_BYTES)

// Pre-converted fp16 embedding table (written by convert kernel each replay).
__device__ __half2 g_emb_h2[EMB_ROWS * D / 2];

__global__ void convert_table_kernel(const float* __restrict__ emb_table)
{
    const int i = blockIdx.x * blockDim.x + threadIdx.x;   // one half2 per thread
    if (i < EMB_ROWS * D / 2) {
        const float2 v = *reinterpret_cast<const float2*>(emb_table + i * 2);
        g_emb_h2[i] = __floats2half2_rn(v.x, v.y);
    }
}

__global__ __launch_bounds__(BLOCK_THREADS, 1)
void hash_embedding_kernel(const int* __restrict__ x,
                           const float* __restrict__ weight_table,
                           float* __restrict__ out,
                           int ntok)
{
    extern __shared__ char smem[];
    float* s_w   = reinterpret_cast<float*>(smem + OFF_W);
    char*  s_emb = smem + OFF_EMB;          // [256 rows][256 halves] = 512 B/row

    const int tid = threadIdx.x;

    unsigned int smem_base;
    asm("{ .reg .u64 t; cvta.to.shared.u64 t, %1; cvt.u32.u64 %0, t; }"
        : "=r"(smem_base) : "l"(smem));

    // ---- async: bulk-load the pre-converted fp16 table (one thread) ----
    if (tid == 0) {
        asm volatile("mbarrier.init.shared.b64 [%0], 1;"
                     :: "r"(smem_base + OFF_MBAR) : "memory");
        asm volatile("fence.proxy.async.shared::cta;" ::: "memory");
        asm volatile("mbarrier.arrive.expect_tx.shared.b64 _, [%0], %1;"
                     :: "r"(smem_base + OFF_MBAR), "r"((unsigned)EMB_BYTES) : "memory");
        asm volatile(
            "cp.async.bulk.shared::cta.global.mbarrier::complete_tx::bytes "
            "[%0], [%1], %2, [%3];"
            :: "r"(smem_base + OFF_EMB), "l"(g_emb_h2),
               "r"((unsigned)EMB_BYTES), "r"(smem_base + OFF_MBAR)
            : "memory");
    }

    // ---- stage weight table (f32) with plain loads (8.2 KB, cheap) ----
    for (int i = tid; i < W_TABLE; i += BLOCK_THREADS) s_w[i] = weight_table[i];

    __syncthreads();   // weights visible + mbarrier init visible to all

    // wait for the bulk copy (phase 0)
    {
        unsigned int mbar = smem_base + OFF_MBAR;
        unsigned int done;
        asm volatile(
            "{\n\t.reg .pred p;\n\t"
            "mbarrier.try_wait.parity.acquire.cta.shared::cta.b64 p, [%1], 0;\n\t"
            "selp.b32 %0, 1, 0, p;\n\t}"
            : "=r"(done) : "r"(mbar) : "memory");
        if (!done) {
            asm volatile(
                "{\n\t.reg .pred P1;\n\t"
                "WL_%=:\n\t"
                "mbarrier.try_wait.parity.acquire.cta.shared::cta.b64 P1, [%0], 0, 0x989680;\n\t"
                "@P1 bra.uni WD_%=;\n\t"
                "bra.uni WL_%=;\n\t"
                "WD_%=:\n\t}"
                :: "r"(mbar) : "memory");
        }
    }

    const int lane = tid & 31;
    const int gw   = blockIdx.x * WARPS_PER_BLOCK + (tid >> 5);  // global warp id
    const int nw   = GRID_X * WARPS_PER_BLOCK;                   // 4736 warps

    const int offA = lane * 8;          // row bytes for cols [lane*4 .. lane*4+3]
    const int offB = 256 + lane * 8;    // row bytes for cols [128+lane*4 ..]

    const int npairs = ntok >> 1;       // 32768

    int p = gw;
    if (p >= npairs) return;

    // prologue index loads for the first pair (same 128B line)
    int4 xi0 = *reinterpret_cast<const int4*>(x + (long long)(2 * p)     * NUM_HASHES);
    int4 xi1 = *reinterpret_cast<const int4*>(x + (long long)(2 * p + 1) * NUM_HASHES);

    #pragma unroll 1
    for (; p < npairs; p += nw) {
        const int pn = (p + nw < npairs) ? (p + nw) : p;
        const int4 xn0 = *reinterpret_cast<const int4*>(x + (long long)(2 * pn)     * NUM_HASHES);
        const int4 xn1 = *reinterpret_cast<const int4*>(x + (long long)(2 * pn + 1) * NUM_HASHES);

        // per-sample weights (broadcast LDS)
        const float u0 = s_w[xi0.x];
        const float u1 = s_w[xi0.y + 513];
        const float u2 = s_w[xi0.z + 1026];
        const float u3 = s_w[xi0.w + 1539];
        const float v0 = s_w[xi1.x];
        const float v1 = s_w[xi1.y + 513];
        const float v2 = s_w[xi1.z + 1026];
        const float v3 = s_w[xi1.w + 1539];

        // fp16 row bases (idx = x >> 1; 512 B per row)
        const char* p00 = s_emb + ((xi0.x >> 1) << 9);
        const char* p01 = s_emb + ((xi0.y >> 1) << 9);
        const char* p02 = s_emb + ((xi0.z >> 1) << 9);
        const char* p03 = s_emb + ((xi0.w >> 1) << 9);
        const char* p10 = s_emb + ((xi1.x >> 1) << 9);
        const char* p11 = s_emb + ((xi1.y >> 1) << 9);
        const char* p12 = s_emb + ((xi1.z >> 1) << 9);
        const char* p13 = s_emb + ((xi1.w >> 1) << 9);

        // batch all 16 gather loads (16 outstanding LDS.64)
        uint2 gA0[4], gB0[4], gA1[4], gB1[4];
        gA0[0] = *reinterpret_cast<const uint2*>(p00 + offA);
        gA0[1] = *reinterpret_cast<const uint2*>(p01 + offA);
        gA0[2] = *reinterpret_cast<const uint2*>(p02 + offA);
        gA0[3] = *reinterpret_cast<const uint2*>(p03 + offA);
        gA1[0] = *reinterpret_cast<const uint2*>(p10 + offA);
        gA1[1] = *reinterpret_cast<const uint2*>(p11 + offA);
        gA1[2] = *reinterpret_cast<const uint2*>(p12 + offA);
        gA1[3] = *reinterpret_cast<const uint2*>(p13 + offA);
        gB0[0] = *reinterpret_cast<const uint2*>(p00 + offB);
        gB0[1] = *reinterpret_cast<const uint2*>(p01 + offB);
        gB0[2] = *reinterpret_cast<const uint2*>(p02 + offB);
        gB0[3] = *reinterpret_cast<const uint2*>(p03 + offB);
        gB1[0] = *reinterpret_cast<const uint2*>(p10 + offB);
        gB1[1] = *reinterpret_cast<const uint2*>(p11 + offB);
        gB1[2] = *reinterpret_cast<const uint2*>(p12 + offB);
        gB1[3] = *reinterpret_cast<const uint2*>(p13 + offB);

        const float wt0[4] = {u0, u1, u2, u3};
        const float wt1[4] = {v0, v1, v2, v3};

        float a0[4] = {0.f, 0.f, 0.f, 0.f};
        float b0[4] = {0.f, 0.f, 0.f, 0.f};
        float a1[4] = {0.f, 0.f, 0.f, 0.f};
        float b1[4] = {0.f, 0.f, 0.f, 0.f};

        #pragma unroll
        for (int h = 0; h < 4; ++h) {
            float2 f0 = __half22float2(*reinterpret_cast<__half2*>(&gA0[h].x));
            float2 f1 = __half22float2(*reinterpret_cast<__half2*>(&gA0[h].y));
            a0[0] += wt0[h] * f0.x;  a0[1] += wt0[h] * f0.y;
            a0[2] += wt0[h] * f1.x;  a0[3] += wt0[h] * f1.y;

            float2 g0 = __half22float2(*reinterpret_cast<__half2*>(&gB0[h].x));
            float2 g1 = __half22float2(*reinterpret_cast<__half2*>(&gB0[h].y));
            b0[0] += wt0[h] * g0.x;  b0[1] += wt0[h] * g0.y;
            b0[2] += wt0[h] * g1.x;  b0[3] += wt0[h] * g1.y;

            float2 h0 = __half22float2(*reinterpret_cast<__half2*>(&gA1[h].x));
            float2 h1 = __half22float2(*reinterpret_cast<__half2*>(&gA1[h].y));
            a1[0] += wt1[h] * h0.x;  a1[1] += wt1[h] * h0.y;
            a1[2] += wt1[h] * h1.x;  a1[3] += wt1[h] * h1.y;

            float2 k0 = __half22float2(*reinterpret_cast<__half2*>(&gB1[h].x));
            float2 k1 = __half22float2(*reinterpret_cast<__half2*>(&gB1[h].y));
            b1[0] += wt1[h] * k0.x;  b1[1] += wt1[h] * k0.y;
            b1[2] += wt1[h] * k1.x;  b1[3] += wt1[h] * k1.y;
        }

        float* op = out + (long long)(2 * p) * D + lane * 4;
        *reinterpret_cast<float4*>(op)       = make_float4(a0[0], a0[1], a0[2], a0[3]);
        *reinterpret_cast<float4*>(op + 128) = make_float4(b0[0], b0[1], b0[2], b0[3]);
        *reinterpret_cast<float4*>(op + 256) = make_float4(a1[0], a1[1], a1[2], a1[3]);
        *reinterpret_cast<float4*>(op + 384) = make_float4(b1[0], b1[1], b1[2], b1[3]);

        xi0 = xn0;
        xi1 = xn1;
    }
}

extern "C" void kernel_launch(void* const* d_in, const int* in_sizes, int n_in,
                              void* d_out, int out_size)
{
    const int*   x            = (const int*)d_in[0];
    const float* weight_table = (const float*)d_in[1];
    const float* emb_table    = (const float*)d_in[2];
    float*       out          = (float*)d_out;

    const int ntok = in_sizes[0] / NUM_HASHES;   // 65536

    // 1) pre-convert the embedding table to fp16 (32768 half2 elements)
    convert_table_kernel<<<(EMB_ROWS * D / 2 + 255) / 256, 256>>>(emb_table);

    // 2) main kernel
    cudaFuncSetAttribute(hash_embedding_kernel,
                         cudaFuncAttributeMaxDynamicSharedMemorySize, SMEM_BYTES);
    hash_embedding_kernel<<<GRID_X, BLOCK_THREADS, SMEM_BYTES>>>(
        x, weight_table, out, ntok);
}